// round 17
// baseline (speedup 1.0000x reference)
#include <cuda_runtime.h>
#include <cuda_fp16.h>
#include <cstdint>
#include <math.h>

#define BATCH 256
#define SEQ   512
#define FEAT  26
#define HID   512
#define MLPH  256
#define NCLS  20
#define LBLK  128          // LSTM blocks
#define WBLK  20           // mlp1 worker blocks
#define NJOBS (SEQ * 16)   // 16 mlp1 tiles per timestep

// ---------------- device scratch (no allocations) ----------------
// g_hs is T-MAJOR: [t][b][HID]
__device__ __half  g_hs[(size_t)SEQ * BATCH * HID];      // 128 MB
__device__ __half  g_hid_h[(size_t)BATCH * SEQ * MLPH];  // 64 MB
__device__ __half  g_whh_h[4 * HID * HID];               // 2 MB
__device__ __half  g_wih_h[4 * HID * 64];                // 256 KB (K padded 26->64)
__device__ __half  g_w1_h[MLPH * HID];                   // 256 KB
__device__ __half  g_x_h[(size_t)BATCH * SEQ * 64];      // 16 MB (F padded 26->64)
__device__ float   g_bias[4 * HID];
__device__ unsigned g_cntv[4 * 32];                      // 4 group counters, 128B apart

// ---------------- asm helpers ----------------
__device__ __forceinline__ void mma_f16_frag(float c[4],
                                             uint32_t a0, uint32_t a1, uint32_t a2, uint32_t a3,
                                             uint32_t b0, uint32_t b1) {
    asm volatile(
        "mma.sync.aligned.m16n8k16.row.col.f32.f16.f16.f32 "
        "{%0,%1,%2,%3},{%4,%5,%6,%7},{%8,%9},{%0,%1,%2,%3};\n"
        : "+f"(c[0]), "+f"(c[1]), "+f"(c[2]), "+f"(c[3])
        : "r"(a0), "r"(a1), "r"(a2), "r"(a3), "r"(b0), "r"(b1));
}
__device__ __forceinline__ void ldsm_x4(uint32_t& r0, uint32_t& r1,
                                        uint32_t& r2, uint32_t& r3, uint32_t addr) {
    asm volatile("ldmatrix.sync.aligned.m8n8.x4.shared.b16 {%0,%1,%2,%3}, [%4];"
                 : "=r"(r0), "=r"(r1), "=r"(r2), "=r"(r3) : "r"(addr));
}
__device__ __forceinline__ uint32_t smem_u32(const void* p) {
    uint32_t a;
    asm("{ .reg .u64 t; cvta.to.shared.u64 t, %1; cvt.u32.u64 %0, t; }" : "=r"(a) : "l"(p));
    return a;
}
__device__ __forceinline__ unsigned ld_acquire(const unsigned* p) {
    unsigned v;
    asm volatile("ld.acquire.gpu.u32 %0, [%1];" : "=r"(v) : "l"(p) : "memory");
    return v;
}
__device__ __forceinline__ void red_release_add(unsigned* p, unsigned v) {
    asm volatile("red.release.gpu.global.add.u32 [%0], %1;" :: "l"(p), "r"(v) : "memory");
}
__device__ __forceinline__ void cp_async16(uint32_t saddr, const void* gaddr) {
    asm volatile("cp.async.cg.shared.global [%0], [%1], 16;" :: "r"(saddr), "l"(gaddr));
}
#define CP_COMMIT() asm volatile("cp.async.commit_group;" ::: "memory")
#define CP_WAIT(n)  asm volatile("cp.async.wait_group %0;" :: "n"(n) : "memory")

__device__ __forceinline__ float tanha(float x) {
    float y;
    asm("tanh.approx.f32 %0, %1;" : "=f"(y) : "f"(x));
    return y;
}
__device__ __forceinline__ float sigm(float x) { return 0.5f * tanha(0.5f * x) + 0.5f; }

// ---------------- LSTM tile geometry ----------------
#define ROWW        36
#define CHUNK_WORDS (64 * ROWW)
#define CHUNK_BYTES (CHUNK_WORDS * 4)    // 9216
#define NCH         9
#define DSMEM       (2 * NCH * CHUNK_BYTES)   // 165,888 B

// 32x32 warp tile, one K=64 chunk (4 k16-steps), fragments via ldmatrix.x4.
__device__ __forceinline__ void mma_chunk64(float acc[2][4][4],
                                            uint32_t aAddr, uint32_t bAddr) {
#pragma unroll
    for (int s = 0; s < 4; s++) {
        uint32_t a[2][4];
#pragma unroll
        for (int mb = 0; mb < 2; mb++)
            ldsm_x4(a[mb][0], a[mb][1], a[mb][2], a[mb][3],
                    aAddr + (uint32_t)((mb * 16 * ROWW + s * 8) * 4));
        uint32_t b[4][2];
#pragma unroll
        for (int p = 0; p < 2; p++) {
            uint32_t r0, r1, r2, r3;
            ldsm_x4(r0, r1, r2, r3, bAddr + (uint32_t)((p * 16 * ROWW + s * 8) * 4));
            b[2 * p][0] = r0; b[2 * p][1] = r1;
            b[2 * p + 1][0] = r2; b[2 * p + 1][1] = r3;
        }
#pragma unroll
        for (int mb = 0; mb < 2; mb++)
#pragma unroll
            for (int nb = 0; nb < 4; nb++)
                mma_f16_frag(acc[mb][nb], a[mb][0], a[mb][1], a[mb][2], a[mb][3],
                             b[nb][0], b[nb][1]);
    }
}

// ---------------- prep ----------------
__global__ void prep_kernel(const float* __restrict__ w_ih, const float* __restrict__ w_hh,
                            const float* __restrict__ b_ih, const float* __restrict__ b_hh,
                            const float* __restrict__ w1) {
    long i = (long)blockIdx.x * blockDim.x + threadIdx.x;
    if (i < (long)4 * HID * HID) g_whh_h[i] = __float2half_rn(w_hh[i]);
    if (i < (long)MLPH * HID)    g_w1_h[i]  = __float2half_rn(w1[i]);
    if (i < (long)4 * HID * 64) {
        int r = (int)(i >> 6), c = (int)(i & 63);
        g_wih_h[i] = __float2half_rn(c < FEAT ? w_ih[r * FEAT + c] : 0.0f);
    }
    if (i < 4 * HID) g_bias[i] = b_ih[i] + b_hh[i];
    if (i < 4 * 32) g_cntv[i] = 0u;
}

__global__ void prepx_kernel(const float* __restrict__ x) {
    long i = (long)blockIdx.x * blockDim.x + threadIdx.x;
    if (i < (long)BATCH * SEQ * 64) {
        long bs = i >> 6;
        int  c  = (int)(i & 63);
        g_x_h[i] = __float2half_rn(c < FEAT ? x[bs * FEAT + c] : 0.0f);
    }
}

// ---------------- worker: mlp1 tile GEMM (16x32 warp tiles, proven path) ----------------
#define KP2 20
__device__ __forceinline__ void mma_chunk(float acc[4][4],
                                          const uint32_t* __restrict__ A,
                                          const uint32_t* __restrict__ B,
                                          int wm, int wn, int lane) {
    const int g  = lane >> 2;
    const int tg = lane & 3;
#pragma unroll
    for (int s = 0; s < 2; s++) {
        const int kk = s * 8 + tg;
        const int ar = wm * 16 + g;
        uint32_t a0 = A[ar * KP2 + kk];
        uint32_t a1 = A[(ar + 8) * KP2 + kk];
        uint32_t a2 = A[ar * KP2 + kk + 4];
        uint32_t a3 = A[(ar + 8) * KP2 + kk + 4];
#pragma unroll
        for (int nn = 0; nn < 4; nn++) {
            const int br = wn * 32 + nn * 8 + g;
            mma_f16_frag(acc[nn], a0, a1, a2, a3, B[br * KP2 + kk], B[br * KP2 + kk + 4]);
        }
    }
}

__device__ void mlp1_worker(uint32_t* dsm, int widx, const float* __restrict__ b1) {
    uint32_t (*As)[64][KP2] = reinterpret_cast<uint32_t(*)[64][KP2]>(dsm);
    uint32_t (*Bs)[64][KP2] = reinterpret_cast<uint32_t(*)[64][KP2]>(dsm + 2 * 64 * KP2);

    const int tid  = threadIdx.x;
    const int lane = tid & 31;
    const int warp = tid >> 5;
    const int wm   = warp >> 1;
    const int wn   = warp & 1;
    const int r0 = tid >> 2;
    const int sg = tid & 3;

    for (int j = widx; j < NJOBS; j += WBLK) {
        const int t  = j >> 4;
        const int sub = j & 15;
        const int bt = sub >> 2;
        const int nt = sub & 3;
        const long row0 = (long)t * BATCH + bt * 64;
        const int  n0   = nt * 64;

        // wait for group bt's step t to be published
        if (tid == 0) {
            while (ld_acquire(&g_cntv[bt * 32]) < 32u * (unsigned)(t + 1)) __nanosleep(128);
        }
        __syncthreads();

        float acc[4][4];
#pragma unroll
        for (int i = 0; i < 4; i++)
#pragma unroll
            for (int k = 0; k < 4; k++) acc[i][k] = 0.0f;

        int4 aR = *reinterpret_cast<const int4*>(g_hs + (row0 + r0) * HID + sg * 8);
        int4 bR = *reinterpret_cast<const int4*>(g_w1_h + (long)(n0 + r0) * HID + sg * 8);
        *reinterpret_cast<int4*>(&As[0][r0][sg * 4]) = aR;
        *reinterpret_cast<int4*>(&Bs[0][r0][sg * 4]) = bR;
        __syncthreads();

        const int NK = HID / 32;
        for (int kc = 0; kc < NK; kc++) {
            if (kc + 1 < NK) {
                aR = *reinterpret_cast<const int4*>(
                         g_hs + (row0 + r0) * HID + (kc + 1) * 32 + sg * 8);
                bR = *reinterpret_cast<const int4*>(
                         g_w1_h + (long)(n0 + r0) * HID + (kc + 1) * 32 + sg * 8);
            }
            mma_chunk(acc, &As[kc & 1][0][0], &Bs[kc & 1][0][0], wm, wn, lane);
            if (kc + 1 < NK) {
                const int nb = (kc + 1) & 1;
                __syncthreads();
                *reinterpret_cast<int4*>(&As[nb][r0][sg * 4]) = aR;
                *reinterpret_cast<int4*>(&Bs[nb][r0][sg * 4]) = bR;
                __syncthreads();
            }
        }

        {
            const int cq = 2 * (lane & 3);
            const long rr = row0 + wm * 16 + (lane >> 2);
#pragma unroll
            for (int nn = 0; nn < 4; nn++) {
                const int col = n0 + wn * 32 + nn * 8 + cq;
                float bb0 = b1[col], bb1 = b1[col + 1];
                __half2 v0 = __floats2half2_rn(fmaxf(acc[nn][0] + bb0, 0.0f),
                                               fmaxf(acc[nn][1] + bb1, 0.0f));
                __half2 v1 = __floats2half2_rn(fmaxf(acc[nn][2] + bb0, 0.0f),
                                               fmaxf(acc[nn][3] + bb1, 0.0f));
                *reinterpret_cast<__half2*>(g_hid_h + rr * MLPH + col)       = v0;
                *reinterpret_cast<__half2*>(g_hid_h + (rr + 8) * MLPH + col) = v1;
            }
        }
        __syncthreads();   // buffers reused next job
    }
}

// ---------------- LSTM block body ----------------
// B column n = wn*32 + gate*8 + iu; unit_local = wn*8 + iu. After merge the
// kg0 thread holds all 4 gates for its (row, unit) pairs -> gate update in regs.
__device__ void lstm_block(uint32_t* dsm, int blk) {
    uint32_t* Bw = dsm;                        // 9 chunks x 64 x 36 words
    uint32_t* Aq = dsm + NCH * CHUNK_WORDS;    // 9 slots  x 64 x 36 words
    __shared__ float zs[64][68];

    const int tid  = threadIdx.x;
    const int lane = tid & 31;
    const int warp = tid >> 5;
    const int wq   = warp & 3;
    const int kg   = warp >> 2;                // k-group 0/1
    const int wmoff = (wq >> 1) * 32;
    const int wn    = wq & 1;
    const int wnoff = wn * 32;
    const int mb   = blk & 3;
    const int m0   = mb * 64;
    const int u0   = (blk >> 2) * 16;

    const int r0 = tid >> 2;
    const int sg = tid & 3;

    // --- resident weight tiles (gate-interleaved columns) ---
    for (int idx = tid; idx < 64 * 72; idx += 256) {
        const int row   = idx / 72;
        const int piece = idx - row * 72;
        const int ch    = piece >> 3;
        const int pc    = piece & 7;
        const int k     = ch * 64 + pc * 8;
        // row -> (wn=row>>5, gate=(row>>3)&3, iu=row&7)
        const int wr = (((row >> 3) & 3)) * HID + u0 + (row >> 5) * 8 + (row & 7);
        int4 v;
        if (ch < 8) v = *reinterpret_cast<const int4*>(g_whh_h + (long)wr * HID + k);
        else        v = *reinterpret_cast<const int4*>(g_wih_h + (long)wr * 64 + (k - 512));
        *reinterpret_cast<int4*>(&Bw[ch * CHUNK_WORDS + row * ROWW + pc * 4]) = v;
    }

    // bias in registers (kg0 threads): breg[gate][q], units u0 + wn*8 + 2*(lane&3) + q
    float breg[4][2];
    {
        const int ul = u0 + wn * 8 + 2 * (lane & 3);
#pragma unroll
        for (int g = 0; g < 4; g++) {
            breg[g][0] = g_bias[g * HID + ul];
            breg[g][1] = g_bias[g * HID + ul + 1];
        }
    }
    __syncthreads();

    const uint32_t aq_base = smem_u32(Aq);
    const uint32_t bw_base = smem_u32(Bw);

    const uint32_t laneA =
        (uint32_t)(((wmoff + (lane & 7) + ((lane >> 3) & 1) * 8) * ROWW +
                    (lane >> 4) * 4) * 4);
    const uint32_t laneB =
        (uint32_t)(((wnoff + (lane >> 4) * 8 + (lane & 7)) * ROWW +
                    ((lane >> 3) & 1) * 4) * 4);

    const uint32_t dstp0 = (uint32_t)((r0 * ROWW + (sg * 2 + 0) * 4) * 4);
    const uint32_t dstp1 = (uint32_t)((r0 * ROWW + (sg * 2 + 1) * 4) * 4);

    // cell state (kg0): creg[mb*4 + dr*2 + q]
    float creg[8];
#pragma unroll
    for (int i = 0; i < 8; i++) creg[i] = 0.0f;

    unsigned target = 0;
    unsigned* cnt = &g_cntv[mb * 32];
    const __half* xrowp = g_x_h + (long)(m0 + r0) * SEQ * 64;

    for (int t = 0; t < SEQ; t++) {
        float acc[2][4][4];
#pragma unroll
        for (int i = 0; i < 2; i++)
#pragma unroll
            for (int j = 0; j < 4; j++)
#pragma unroll
                for (int k = 0; k < 4; k++) acc[i][j][k] = 0.0f;

        // x load (independent of h), group 0
        {
            const __half* xs = xrowp + (long)t * 64;
            cp_async16(aq_base + 8 * CHUNK_BYTES + dstp0, xs + (sg * 2 + 0) * 8);
            cp_async16(aq_base + 8 * CHUNK_BYTES + dstp1, xs + (sg * 2 + 1) * 8);
            CP_COMMIT();
        }

        if (t > 0) {
            target += 32;
            if (tid == 0) { while (ld_acquire(cnt) < target) {} }
        }
        __syncthreads();

        if (t > 0) {
            const __half* hs = g_hs + ((long)(t - 1) * BATCH + (m0 + r0)) * HID;
#pragma unroll
            for (int c = 0; c < 8; c++) {
                cp_async16(aq_base + c * CHUNK_BYTES + dstp0, hs + c * 64 + (sg * 2 + 0) * 8);
                cp_async16(aq_base + c * CHUNK_BYTES + dstp1, hs + c * 64 + (sg * 2 + 1) * 8);
                CP_COMMIT();
            }
            CP_WAIT(8);
        } else {
            CP_WAIT(0);
        }
        __syncthreads();

        // x chunk (chunk 8, owner kg0)
        if (kg == 0)
            mma_chunk64(acc, aq_base + 8 * CHUNK_BYTES + laneA,
                        bw_base + 8 * CHUNK_BYTES + laneB);

        if (t > 0) {
#define STEP_CHUNK(c, w)                                                     \
            CP_WAIT(w);                                                      \
            __syncthreads();                                                 \
            if (((c) & 1) == kg)                                             \
                mma_chunk64(acc, aq_base + (c) * CHUNK_BYTES + laneA,        \
                            bw_base + (c) * CHUNK_BYTES + laneB);
            STEP_CHUNK(0, 7) STEP_CHUNK(1, 6) STEP_CHUNK(2, 5) STEP_CHUNK(3, 4)
            STEP_CHUNK(4, 3) STEP_CHUNK(5, 2) STEP_CHUNK(6, 1) STEP_CHUNK(7, 0)
#undef STEP_CHUNK
        }
        __syncthreads();

        // merge: kg1 stores partials, kg0 adds into regs (no write-back)
        if (kg == 1) {
#pragma unroll
            for (int mbi = 0; mbi < 2; mbi++)
#pragma unroll
                for (int nb = 0; nb < 4; nb++) {
                    const int row = wmoff + mbi * 16 + (lane >> 2);
                    const int col = wnoff + nb * 8 + 2 * (lane & 3);
                    *reinterpret_cast<float2*>(&zs[row][col]) =
                        make_float2(acc[mbi][nb][0], acc[mbi][nb][1]);
                    *reinterpret_cast<float2*>(&zs[row + 8][col]) =
                        make_float2(acc[mbi][nb][2], acc[mbi][nb][3]);
                }
        }
        __syncthreads();

        if (kg == 0) {
            // add partner partials
#pragma unroll
            for (int mbi = 0; mbi < 2; mbi++)
#pragma unroll
                for (int nb = 0; nb < 4; nb++) {
                    const int row = wmoff + mbi * 16 + (lane >> 2);
                    const int col = wnoff + nb * 8 + 2 * (lane & 3);
                    float2 v0 = *reinterpret_cast<float2*>(&zs[row][col]);
                    float2 v1 = *reinterpret_cast<float2*>(&zs[row + 8][col]);
                    acc[mbi][nb][0] += v0.x; acc[mbi][nb][1] += v0.y;
                    acc[mbi][nb][2] += v1.x; acc[mbi][nb][3] += v1.y;
                }
            // gate update in registers; store h fp16 (t-major)
            const int un = u0 + wn * 8 + 2 * (lane & 3);
#pragma unroll
            for (int mbi = 0; mbi < 2; mbi++) {
#pragma unroll
                for (int dr = 0; dr < 2; dr++) {
                    float ho[2];
#pragma unroll
                    for (int q = 0; q < 2; q++) {
                        const int ai = dr * 2 + q;
                        float zi = acc[mbi][0][ai] + breg[0][q];
                        float zf = acc[mbi][1][ai] + breg[1][q];
                        float zg = acc[mbi][2][ai] + breg[2][q];
                        float zo = acc[mbi][3][ai] + breg[3][q];
                        const int ci = mbi * 4 + dr * 2 + q;
                        float cn = sigm(zf) * creg[ci] + sigm(zi) * tanha(zg);
                        creg[ci] = cn;
                        ho[q] = sigm(zo) * tanha(cn);
                    }
                    __half2 p = __floats2half2_rn(ho[0], ho[1]);
                    const int row = m0 + wmoff + mbi * 16 + (lane >> 2) + dr * 8;
                    *reinterpret_cast<uint32_t*>(
                        g_hs + ((long)t * BATCH + row) * HID + un) =
                        *reinterpret_cast<uint32_t*>(&p);
                }
            }
        }

        __syncthreads();
        if (tid == 0) red_release_add(cnt, 1u);
    }
}

// ---------------- fused persistent kernel ----------------
__global__ void __launch_bounds__(256, 1)
fused_kernel(const float* __restrict__ b1) {
    extern __shared__ uint32_t dsm[];
    if (blockIdx.x < LBLK) lstm_block(dsm, blockIdx.x);
    else                   mlp1_worker(dsm, blockIdx.x - LBLK, b1);
}

// ---------------- MLP layer 2 + log_softmax (unpermutes t-major rows) ----------------
__global__ void __launch_bounds__(256, 2)
mlp2_kernel(const float* __restrict__ w2, const float* __restrict__ b2,
            float* __restrict__ out) {
    __shared__ float w2s[NCLS][MLPH + 1];
    __shared__ float hr[8][MLPH];

    const int tid  = threadIdx.x;
    const int lane = tid & 31;
    const int warp = tid >> 5;

    for (int e = tid; e < NCLS * MLPH; e += 256)
        w2s[e / MLPH][e % MLPH] = w2[e];

    const long row = (long)blockIdx.x * 8 + warp;   // = t*BATCH + b
    for (int k = lane; k < MLPH; k += 32)
        hr[warp][k] = __half2float(g_hid_h[row * MLPH + k]);
    __syncthreads();

    float logit = -1e30f;
    if (lane < NCLS) {
        float s = b2[lane];
#pragma unroll 8
        for (int k = 0; k < MLPH; k++)
            s += hr[warp][k] * w2s[lane][k];
        logit = s;
    }
    float m = logit;
#pragma unroll
    for (int o = 16; o; o >>= 1) m = fmaxf(m, __shfl_xor_sync(0xffffffffu, m, o));
    float e = (lane < NCLS) ? expf(logit - m) : 0.0f;
    float ssum = e;
#pragma unroll
    for (int o = 16; o; o >>= 1) ssum += __shfl_xor_sync(0xffffffffu, ssum, o);
    if (lane < NCLS) {
        const long b = row & (BATCH - 1);
        const long t = row >> 8;
        out[(b * SEQ + t) * NCLS + lane] = logit - m - logf(ssum);
    }
}

// ---------------- launch ----------------
extern "C" void kernel_launch(void* const* d_in, const int* in_sizes, int n_in,
                              void* d_out, int out_size) {
    const float* x    = (const float*)d_in[0];
    const float* w_ih = (const float*)d_in[1];
    const float* w_hh = (const float*)d_in[2];
    const float* b_ih = (const float*)d_in[3];
    const float* b_hh = (const float*)d_in[4];
    const float* w1   = (const float*)d_in[5];
    const float* b1   = (const float*)d_in[6];
    const float* w2   = (const float*)d_in[7];
    const float* b2   = (const float*)d_in[8];
    float* out = (float*)d_out;

    prep_kernel<<<(4 * HID * HID + 255) / 256, 256>>>(w_ih, w_hh, b_ih, b_hh, w1);
    prepx_kernel<<<((long)BATCH * SEQ * 64 + 255) / 256, 256>>>(x);

    cudaFuncSetAttribute(fused_kernel,
                         cudaFuncAttributeMaxDynamicSharedMemorySize, DSMEM);
    fused_kernel<<<LBLK + WBLK, 256, DSMEM>>>(b1);

    mlp2_kernel<<<(BATCH * SEQ) / 8, 256>>>(w2, b2, out);
}